// round 17
// baseline (speedup 1.0000x reference)
#include <cuda_runtime.h>
#include <math.h>
#include <stdint.h>

// Problem constants (fixed by the reference)
#define B_   16
#define E_   1024
#define DIN_ 128
#define P_   2048
#define D_   128
#define LMAX 16
#define G3   384   // 3*D
#define PROJ_STRIDE 512   // gate-interleaved proj row: [e*4 + {z,r,h,pad}]

// ---------------- scratch (device globals: no allocations allowed) ---------
__device__ int      g_lut[P_ * LMAX];                          // path+1 per (p,t), 0 if empty (BSS zero)
__device__ float    g_proj[((size_t)B_ * E_ + 1) * PROJ_STRIDE];  // interleaved proj; row 16384 = zero row
__device__ float    g_hs[(size_t)B_ * P_ * LMAX * D_];         // GRU hidden states (fp32)
__device__ uint32_t g_wrec[G3 * D_];                           // W_rec^T tf32 quad-fragment image
__device__ uint32_t g_wkq_img[D_ * D_];                        // M quad image for m-GEMM
__device__ uint32_t g_wv_img[D_ * D_];                         // Wv quad image for ctx-GEMM

__device__ __forceinline__ float tanha(float x) {
    float r; asm("tanh.approx.f32 %0, %1;" : "=f"(r) : "f"(x)); return r;
}
__device__ __forceinline__ float sigf(float x) { return fmaf(tanha(0.5f * x), 0.5f, 0.5f); }

__device__ __forceinline__ uint32_t f2tf32(float v) {
    uint32_t r;
    asm("cvt.rna.tf32.f32 %0, %1;" : "=r"(r) : "f"(v));
    return r;
}

// quad-fragment word offset within a 128-word row image:
//   off(n,k) = 16*((k>>4)^(n&3)) + 4*(k&3) + 2*((k>>3)&1) + ((k>>2)&1)
__device__ __forceinline__ int quad_off(int n, int k) {
    return 16 * (((k >> 4)) ^ (n & 3)) + 4 * (k & 3) + 2 * ((k >> 3) & 1) + ((k >> 2) & 1);
}

// mma.sync m16n8k8 tf32: D += A*B (fp32 accum)
__device__ __forceinline__ void mma8(float* c, uint32_t a0, uint32_t a1, uint32_t a2, uint32_t a3,
                                     uint32_t b0, uint32_t b1) {
    asm volatile("mma.sync.aligned.m16n8k8.row.col.f32.tf32.tf32.f32 "
                 "{%0,%1,%2,%3}, {%4,%5,%6,%7}, {%8,%9}, {%0,%1,%2,%3};"
                 : "+f"(c[0]), "+f"(c[1]), "+f"(c[2]), "+f"(c[3])
                 : "r"(a0), "r"(a1), "r"(a2), "r"(a3), "r"(b0), "r"(b1));
}

// ---------------- merged prep + proj kernel -----------------------------------
// One launch, all blocks independent:
//   [0,256):        proj 64 rows/CTA (builds its own W_in image in-CTA)
//   [256,352):      W_rec quad image (96 blocks x 512)
//   [352,384):      wkq -> g_wkq_img directly (32 blocks; wk staged in smem)
//   [384,388):      wv  -> g_wv_img (4 blocks)
//   388:            bias0 (zero-input proj row)
//   [389, ...):     lut fill
#define PROJ_SMEM ((G3 * D_ + 64 * D_) * 4)   // 229376
__global__ void __launch_bounds__(512, 1)
k_prep_proj(const float* __restrict__ inp, const float* __restrict__ bin,
            const float* __restrict__ brec, const float* __restrict__ Wrec,
            const float* __restrict__ Win,  const float* __restrict__ wk,
            const float* __restrict__ wq,   const float* __restrict__ wv,
            const int* __restrict__ paths,  const int* __restrict__ idx,
            const int* __restrict__ seqs,   int T) {
    extern __shared__ float sm[];
    int bid = blockIdx.x;
    int tid = threadIdx.x;

    if (bid >= 256) {
        if (bid < 352) {
            // W_rec image: i = (bid-256)*512 + tid over 49152; k = i/384, n = i%384
            int i = (bid - 256) * 512 + tid;
            int k = i / G3, n = i - k * G3;
            g_wrec[n * 128 + quad_off(n, k)] = f2tf32(Wrec[i]);
        } else if (bid < 384) {
            // wkq -> g_wkq_img: acc(dp,d) = sum_e wk[d][e]*wq[dp][e]
            float* wk_s = sm;   // 128*133
            for (int i2 = tid; i2 < D_ * D_; i2 += 512) {
                int d = i2 >> 7, e = i2 & 127;
                wk_s[e * 133 + d] = wk[i2];
            }
            __syncthreads();
            int i = (bid - 352) * 512 + tid;    // 0..16383
            int dp = i >> 7, d = i & 127;
            float acc = 0.f;
            #pragma unroll 4
            for (int e = 0; e < D_; e++) acc += wk_s[e * 133 + d] * wq[dp * D_ + e];
            g_wkq_img[d * 128 + quad_off(d, dp)] = f2tf32(acc);
        } else if (bid < 388) {
            // wv image: i over 16384; k = i>>7, n = i&127
            int i = (bid - 384) * 4096 + tid;
            #pragma unroll
            for (int rep = 0; rep < 8; rep++, i += 512) {
                int k = i >> 7, n = i & 127;
                g_wv_img[n * 128 + quad_off(n, k)] = f2tf32(wv[i]);
            }
        } else if (bid == 388) {
            if (tid < G3) {
                int e = tid & 127, g = tid >> 7;   // g in 0..2
                float v = bin[g * 128 + e];
                if (g < 2) v += brec[g * 128 + e];
                g_proj[(size_t)B_ * E_ * PROJ_STRIDE + e * 4 + g] = v;
            }
        } else {
            int j = (bid - 389) * 512 + tid;
            if (j < T) g_lut[idx[j] * LMAX + seqs[j]] = paths[j] + 1;
        }
        return;
    }

    // ---- proj: 64 rows/CTA via tf32 mma, self-built W_in image ----
    uint32_t* Wb = (uint32_t*)sm;         // 49152 words
    uint32_t* Ab = Wb + G3 * D_;          // 64*128 words

    int w    = tid >> 5, lane = tid & 31;
    int gid  = lane >> 2, tig = lane & 3;
    int xorb = gid & 3;
    int row0 = bid * 64;

    {   // build W_in quad image in-CTA (coalesced LDG, scattered STS) + stage A
        for (int i = tid; i < DIN_ * G3; i += 512) {
            int k = i / G3, n = i - k * G3;
            Wb[n * 128 + quad_off(n, k)] = f2tf32(Win[i]);
        }
        const float* ip = inp + (size_t)row0 * DIN_;
        for (int i = tid; i < 64 * DIN_; i += 512) {
            int r = i >> 7, k = i & 127;
            Ab[r * 128 + quad_off(r, k)] = f2tf32(ip[i]);
        }
    }
    __syncthreads();

    const int ecol = 8 * w + 2 * tig;
    float2 bias[3];
    #pragma unroll
    for (int g = 0; g < 3; g++) {
        int n = g * 128 + ecol;
        bias[g] = *(const float2*)(bin + n);
        if (g < 2) {
            float2 bb2 = *(const float2*)(brec + n);
            bias[g].x += bb2.x; bias[g].y += bb2.y;
        }
    }

    float acc[4][3][4];
    #pragma unroll
    for (int a = 0; a < 4; a++)
        for (int q = 0; q < 3; q++)
            for (int c = 0; c < 4; c++) acc[a][q][c] = 0.f;

    #pragma unroll
    for (int kg = 0; kg < 8; kg++) {
        int koff = 16 * (kg ^ xorb) + 4 * tig;
        uint4 bf[3];
        #pragma unroll
        for (int g = 0; g < 3; g++)
            bf[g] = *(const uint4*)(Wb + (g * 128 + 8 * w + gid) * 128 + koff);
        #pragma unroll
        for (int mt = 0; mt < 4; mt++) {
            int r = 16 * mt + gid;
            uint4 alo = *(const uint4*)(Ab + r * 128 + koff);
            uint4 ahi = *(const uint4*)(Ab + (r + 8) * 128 + koff);
            #pragma unroll
            for (int g = 0; g < 3; g++) {
                mma8(acc[mt][g], alo.x, ahi.x, alo.y, ahi.y, bf[g].x, bf[g].y);
                mma8(acc[mt][g], alo.z, ahi.z, alo.w, ahi.w, bf[g].z, bf[g].w);
            }
        }
    }

    #pragma unroll
    for (int mt = 0; mt < 4; mt++)
        #pragma unroll
        for (int hf = 0; hf < 2; hf++) {
            int r = 16 * mt + 8 * hf + gid;
            float* grow = g_proj + (size_t)(row0 + r) * PROJ_STRIDE;
            *(float4*)(grow + ecol * 4) =
                make_float4(acc[mt][0][hf * 2] + bias[0].x,
                            acc[mt][1][hf * 2] + bias[1].x,
                            acc[mt][2][hf * 2] + bias[2].x, 0.f);
            *(float4*)(grow + ecol * 4 + 4) =
                make_float4(acc[mt][0][hf * 2 + 1] + bias[0].y,
                            acc[mt][1][hf * 2 + 1] + bias[1].y,
                            acc[mt][2][hf * 2 + 1] + bias[2].y, 0.f);
        }
}

// ---------------- fused tf32-HMMA GRU + tensor-core attention -----------------
// (byte-identical to R16)
#define GRU_ROWS 32
#define GRU_SMEM (G3 * D_ * 4 + 2 * GRU_ROWS * D_ * 4 + GRU_ROWS * LMAX * 2)  // 230400
__global__ void __launch_bounds__(512, 1)
k_gru_fused(const float* __restrict__ brec, float* __restrict__ out) {
    extern __shared__ float sm[];
    uint32_t*  Wb   = (uint32_t*)sm;                  // 49152 words
    uint32_t*  hb0  = Wb + G3 * D_;                   // 32*128 words (tf32 bits of h)
    uint32_t*  hb1  = hb0 + GRU_ROWS * D_;            // 32*128 words
    uint16_t*  prow = (uint16_t*)(hb1 + GRU_ROWS * D_);  // 32*16 u16

    int tid  = threadIdx.x;
    int w    = tid >> 5, lane = tid & 31;
    int gid  = lane >> 2, tig = lane & 3;
    int xorb = gid & 3;
    int n0   = blockIdx.x * GRU_ROWS;
    int bb   = n0 >> 11;                // batch index (32 | 2048)
    int p0   = n0 & (P_ - 1);

    {   // stage W image + gather row ids (u16; 16384 = zero row)
        const float4* s = (const float4*)g_wrec;
        float4*       d = (float4*)Wb;
        #pragma unroll 4
        for (int i = tid; i < G3 * D_ / 4; i += 512) d[i] = s[i];
        if (tid < GRU_ROWS * LMAX) {
            int e1 = g_lut[p0 * LMAX + tid];
            prow[tid] = (uint16_t)(e1 > 0 ? (bb * E_ + e1 - 1) : B_ * E_);
        }
    }
    __syncthreads();

    const int ecol = 8 * w + 2 * tig;
    float bh0 = brec[256 + ecol];
    float bh1 = brec[256 + ecol + 1];

    float hold[2][2][2];   // [mt][hf][p]
    #pragma unroll
    for (int a = 0; a < 2; a++)
        for (int b = 0; b < 2; b++)
            for (int c = 0; c < 2; c++) hold[a][b][c] = 0.f;

    const int wsw0 = quad_off(gid, ecol);
    const int wsw1 = quad_off(gid, ecol + 1);

    for (int t = 0; t < LMAX; t++) {
        uint32_t* hcur = (t & 1) ? hb1 : hb0;
        uint32_t* hnxt = (t & 1) ? hb0 : hb1;

        // ---- prefetch x-gates (interleaved proj: one float4 per column) ----
        float4 xq[2][2][2];   // [mt][hf][col p]
        #pragma unroll
        for (int mt = 0; mt < 2; mt++)
            #pragma unroll
            for (int hf = 0; hf < 2; hf++) {
                int r = 16 * mt + 8 * hf + gid;
                const float4* xp = (const float4*)(g_proj + (size_t)prow[r * LMAX + t] * PROJ_STRIDE);
                xq[mt][hf][0] = xp[ecol];
                xq[mt][hf][1] = xp[ecol + 1];
            }

        // ---- gates = h @ W_rec  (tf32 mma, quad LDS.128 fragments) ----
        float acc[2][3][4];
        #pragma unroll
        for (int a = 0; a < 2; a++)
            for (int q = 0; q < 3; q++)
                for (int c = 0; c < 4; c++) acc[a][q][c] = 0.f;

        if (t > 0) {   // h==0 at t=0
            #pragma unroll
            for (int kg = 0; kg < 8; kg++) {
                int koff = 16 * (kg ^ xorb) + 4 * tig;
                uint4 bf[3];
                #pragma unroll
                for (int g = 0; g < 3; g++)
                    bf[g] = *(const uint4*)(Wb + (g * 128 + 8 * w + gid) * 128 + koff);
                #pragma unroll
                for (int mt = 0; mt < 2; mt++) {
                    int r = 16 * mt + gid;
                    uint4 alo = *(const uint4*)(hcur + r * 128 + koff);
                    uint4 ahi = *(const uint4*)(hcur + (r + 8) * 128 + koff);
                    #pragma unroll
                    for (int g = 0; g < 3; g++) {
                        mma8(acc[mt][g], alo.x, ahi.x, alo.y, ahi.y, bf[g].x, bf[g].y);
                        mma8(acc[mt][g], alo.z, ahi.z, alo.w, ahi.w, bf[g].z, bf[g].w);
                    }
                }
            }
        }

        // ---- elementwise GRU update (writes the OTHER buffer) ----
        #pragma unroll
        for (int mt = 0; mt < 2; mt++)
            #pragma unroll
            for (int hf = 0; hf < 2; hf++) {
                int r = 16 * mt + 8 * hf + gid;
                float hn[2];
                #pragma unroll
                for (int p = 0; p < 2; p++) {
                    float4 xc = xq[mt][hf][p];
                    float bhv = p ? bh1 : bh0;
                    float z  = sigf(xc.x + acc[mt][0][hf * 2 + p]);
                    float rr = sigf(xc.y + acc[mt][1][hf * 2 + p]);
                    float hc = tanha(xc.z + rr * (acc[mt][2][hf * 2 + p] + bhv));
                    float hv = z * hold[mt][hf][p] + (1.0f - z) * hc;
                    hold[mt][hf][p] = hv;
                    hn[p] = hv;
                }
                hnxt[r * 128 + wsw0] = f2tf32(hn[0]);
                hnxt[r * 128 + wsw1] = f2tf32(hn[1]);
                __stcs((float2*)(g_hs + (size_t)(n0 + r) * (LMAX * D_) + t * D_ + ecol),
                       make_float2(hn[0], hn[1]));
            }
        __syncthreads();
    }
    // after t=15: hb0 holds tf32 fragments of last = h(15)

    // ============ tensor-core attention epilogue ============
    uint32_t* wkqI = Wb;
    uint32_t* wvI  = Wb + 16384;
    float*    mS   = (float*)hb1;
    {
        const float4* s1 = (const float4*)g_wkq_img;
        const float4* s2 = (const float4*)g_wv_img;
        float4*       d1 = (float4*)wkqI;
        float4*       d2 = (float4*)wvI;
        #pragma unroll
        for (int i = tid; i < 4096; i += 512) { d1[i] = s1[i]; d2[i] = s2[i]; }
    }
    __syncthreads();

    // ---- m-GEMM: m[32x128] = last(hb0) @ M. Warp w covers d-cols [8w,8w+8).
    {
        float am[2][4];
        #pragma unroll
        for (int a = 0; a < 2; a++)
            for (int c = 0; c < 4; c++) am[a][c] = 0.f;
        #pragma unroll
        for (int kg = 0; kg < 8; kg++) {
            int koff = 16 * (kg ^ xorb) + 4 * tig;
            uint4 bf = *(const uint4*)(wkqI + (8 * w + gid) * 128 + koff);
            #pragma unroll
            for (int mt = 0; mt < 2; mt++) {
                int r = 16 * mt + gid;
                uint4 alo = *(const uint4*)(hb0 + r * 128 + koff);
                uint4 ahi = *(const uint4*)(hb0 + (r + 8) * 128 + koff);
                mma8(am[mt], alo.x, ahi.x, alo.y, ahi.y, bf.x, bf.y);
                mma8(am[mt], alo.z, ahi.z, alo.w, ahi.w, bf.z, bf.w);
            }
        }
        #pragma unroll
        for (int mt = 0; mt < 2; mt++)
            #pragma unroll
            for (int hf = 0; hf < 2; hf++) {
                int r = 16 * mt + 8 * hf + gid;
                *(float2*)(mS + r * 128 + ecol)
                    = make_float2(am[mt][hf * 2], am[mt][hf * 2 + 1]);
            }
    }
    __syncthreads();

    // ---- att/u per warp (rows 2w, 2w+1): u = sum_l (h_l . m) h_l ----
    float4 uvec[2];
    #pragma unroll
    for (int rr = 0; rr < 2; rr++) {
        int r = 2 * w + rr;
        const float4* g4 = (const float4*)(g_hs + (size_t)(n0 + r) * (LMAX * D_));
        float4 m4 = *(const float4*)(mS + r * 128 + 4 * lane);
        float4 u  = make_float4(0.f, 0.f, 0.f, 0.f);
        #pragma unroll
        for (int l = 0; l < LMAX; l++) {
            float4 h4 = __ldcs(g4 + l * 32 + lane);
            float  pp = m4.x * h4.x + m4.y * h4.y + m4.z * h4.z + m4.w * h4.w;
            #pragma unroll
            for (int o = 16; o > 0; o >>= 1) pp += __shfl_xor_sync(0xffffffffu, pp, o);
            u.x = fmaf(pp, h4.x, u.x); u.y = fmaf(pp, h4.y, u.y);
            u.z = fmaf(pp, h4.z, u.z); u.w = fmaf(pp, h4.w, u.w);
        }
        uvec[rr] = u;
    }
    #pragma unroll
    for (int rr = 0; rr < 2; rr++) {
        int r = 2 * w + rr;
        hb0[r * 128 + quad_off(r, 4 * lane + 0)] = f2tf32(uvec[rr].x);
        hb0[r * 128 + quad_off(r, 4 * lane + 1)] = f2tf32(uvec[rr].y);
        hb0[r * 128 + quad_off(r, 4 * lane + 2)] = f2tf32(uvec[rr].z);
        hb0[r * 128 + quad_off(r, 4 * lane + 3)] = f2tf32(uvec[rr].w);
    }
    __syncthreads();

    // ---- ctx-GEMM: out[32x128] = u(hb0) @ Wv. Warp w covers n-cols [8w,8w+8).
    {
        float ac[2][4];
        #pragma unroll
        for (int a = 0; a < 2; a++)
            for (int c = 0; c < 4; c++) ac[a][c] = 0.f;
        #pragma unroll
        for (int kg = 0; kg < 8; kg++) {
            int koff = 16 * (kg ^ xorb) + 4 * tig;
            uint4 bf = *(const uint4*)(wvI + (8 * w + gid) * 128 + koff);
            #pragma unroll
            for (int mt = 0; mt < 2; mt++) {
                int r = 16 * mt + gid;
                uint4 alo = *(const uint4*)(hb0 + r * 128 + koff);
                uint4 ahi = *(const uint4*)(hb0 + (r + 8) * 128 + koff);
                mma8(ac[mt], alo.x, ahi.x, alo.y, ahi.y, bf.x, bf.y);
                mma8(ac[mt], alo.z, ahi.z, alo.w, ahi.w, bf.z, bf.w);
            }
        }
        #pragma unroll
        for (int mt = 0; mt < 2; mt++)
            #pragma unroll
            for (int hf = 0; hf < 2; hf++) {
                int r = 16 * mt + 8 * hf + gid;
                *(float2*)(out + (size_t)(n0 + r) * 128 + ecol)
                    = make_float2(ac[mt][hf * 2], ac[mt][hf * 2 + 1]);
            }
    }
}

// ---------------- launch -----------------------------------------------------
extern "C" void kernel_launch(void* const* d_in, const int* in_sizes, int n_in,
                              void* d_out, int out_size) {
    const float* inputs = (const float*)d_in[0];
    const float* W_in   = (const float*)d_in[1];
    const float* W_rec  = (const float*)d_in[2];
    const float* b_in   = (const float*)d_in[3];
    const float* b_rec  = (const float*)d_in[4];
    const float* wq     = (const float*)d_in[5];
    const float* wk     = (const float*)d_in[6];
    const float* wv     = (const float*)d_in[7];
    const int*   paths  = (const int*)d_in[8];
    const int*   idx    = (const int*)d_in[9];
    const int*   seqs   = (const int*)d_in[10];
    int T = in_sizes[8];

    cudaFuncSetAttribute(k_prep_proj, cudaFuncAttributeMaxDynamicSharedMemorySize, PROJ_SMEM);
    cudaFuncSetAttribute(k_gru_fused, cudaFuncAttributeMaxDynamicSharedMemorySize, GRU_SMEM);

    int lut_blocks = (T + 511) / 512;
    k_prep_proj<<<389 + lut_blocks, 512, PROJ_SMEM>>>(inputs, b_in, b_rec, W_rec, W_in,
                                                      wk, wq, wv, paths, idx, seqs, T);
    k_gru_fused<<<(B_ * P_) / GRU_ROWS, 512, GRU_SMEM>>>(b_rec, (float*)d_out);
}